// round 12
// baseline (speedup 1.0000x reference)
#include <cuda_runtime.h>
#include <cstdint>
#include <cstddef>

#define BATCH 8
#define HH 56
#define WW 56
#define CCH 384
#define HEADS 6
#define DH 64
#define PQ 784
#define SS 196
#define TT 784

__device__ float g_Qln[BATCH * PQ * CCH];
__device__ float g_KV [BATCH * PQ * CCH];
__device__ float g_Qh [BATCH * PQ * CCH];
__device__ float g_Kh [BATCH * PQ * CCH];
__device__ float g_Vh [BATCH * PQ * CCH];
__device__ float g_Rm [BATCH * HEADS * SS * TT];
__device__ float g_AV [BATCH * PQ * CCH];

// ---------------- mma helpers ----------------
__device__ __forceinline__ uint32_t f2tf(float f) {
    uint32_t r; asm("cvt.rna.tf32.f32 %0, %1;" : "=r"(r) : "f"(f)); return r;
}
__device__ __forceinline__ uint32_t bf2(float lo, float hi) {
    uint32_t r; asm("cvt.rn.bf16x2.f32 %0, %1, %2;" : "=r"(r) : "f"(hi), "f"(lo)); return r;
}
__device__ __forceinline__ void mma8(float* d, const uint32_t* a, uint32_t b0, uint32_t b1) {
    asm volatile("mma.sync.aligned.m16n8k8.row.col.f32.tf32.tf32.f32 "
        "{%0,%1,%2,%3}, {%4,%5,%6,%7}, {%8,%9}, {%0,%1,%2,%3};"
        : "+f"(d[0]), "+f"(d[1]), "+f"(d[2]), "+f"(d[3])
        : "r"(a[0]), "r"(a[1]), "r"(a[2]), "r"(a[3]), "r"(b0), "r"(b1));
}
__device__ __forceinline__ void mma16(float* d, const uint32_t* a, uint32_t b0, uint32_t b1) {
    asm volatile("mma.sync.aligned.m16n8k16.row.col.f32.bf16.bf16.f32 "
        "{%0,%1,%2,%3}, {%4,%5,%6,%7}, {%8,%9}, {%0,%1,%2,%3};"
        : "+f"(d[0]), "+f"(d[1]), "+f"(d[2]), "+f"(d[3])
        : "r"(a[0]), "r"(a[1]), "r"(a[2]), "r"(a[3]), "r"(b0), "r"(b1));
}

// flash smem map (bytes)
#define OFF_Q   0          // Q bf16 [128][196 u32] raw (unscaled)
#define OFF_K   100352     // K bf16 [32][196 u32]
#define OFF_P   125440     // P tf32, per-o [128][36 u32], 2 o's
#define OFF_V   162304     // V tf32 [32][136 u32] (o-pair's 128 ch + pad)
#define OFF_RM  179712     // [2o][2wn][128] f32
#define OFF_RS  183808     // [2o][2wn][128] f32
#define OFF_B0  187904
#define OFF_B1  188416
#define OFF_B2  188928
#define OFF_B3  189440
#define OFF_WXA 189952
#define OFF_WYA 190464
#define SMT     190976

// gemm_tc smem (64-row m-tile)
#define GOFF_A 0
#define GOFF_B 33792
#define GSMT   101376

// ---------------- kernel 1: depthwise conv + LN + 2x2 avgpool ----------------
__global__ void prep_k(const float* __restrict__ x, const float* __restrict__ cw,
                       const float* __restrict__ lng, const float* __restrict__ lnb,
                       float* __restrict__ Qln, float* __restrict__ KV)
{
    int p = blockIdx.x, b = blockIdx.y, c = threadIdx.x;
    int oy = p / 28, ox = p % 28;
    const float* xb = x + (size_t)b * (HH * WW) * CCH;
    float acc = 0.f;
    #pragma unroll
    for (int dy = 0; dy < 3; dy++) {
        int y = 2 * oy + dy - 1;
        if ((unsigned)y < (unsigned)HH) {
            #pragma unroll
            for (int dx = 0; dx < 3; dx++) {
                int xx = 2 * ox + dx - 1;
                if ((unsigned)xx < (unsigned)WW)
                    acc += xb[(size_t)(y * WW + xx) * CCH + c] * cw[c * 9 + dy * 3 + dx];
            }
        }
    }
    int py = 2 * oy, px = 2 * ox;
    float pv = 0.25f * (xb[(size_t)(py * WW + px) * CCH + c] +
                        xb[(size_t)(py * WW + px + 1) * CCH + c] +
                        xb[(size_t)((py + 1) * WW + px) * CCH + c] +
                        xb[(size_t)((py + 1) * WW + px + 1) * CCH + c]);
    KV[((size_t)b * PQ + p) * CCH + c] = pv;

    __shared__ float ssum[CCH], ssq[CCH];
    ssum[c] = acc; ssq[c] = acc * acc;
    __syncthreads();
    if (c < 128) { ssum[c] += ssum[c + 128] + ssum[c + 256];
                   ssq [c] += ssq [c + 128] + ssq [c + 256]; }
    __syncthreads();
    for (int s = 64; s > 0; s >>= 1) {
        if (c < s) { ssum[c] += ssum[c + s]; ssq[c] += ssq[c + s]; }
        __syncthreads();
    }
    float mu  = ssum[0] * (1.f / CCH);
    float var = ssq[0] * (1.f / CCH) - mu * mu;
    float inv = rsqrtf(var + 1e-5f);
    Qln[((size_t)b * PQ + p) * CCH + c] = (acc - mu) * inv * lng[c] + lnb[c];
}

// ---------------- kernel 2a: tf32 tensor GEMM (64x128 tile) ------------------
__global__ void __launch_bounds__(256, 2) gemm_tc(const float* __restrict__ A,
                                                  const float* __restrict__ W,
                                                  const float* __restrict__ bias,
                                                  float* __restrict__ C, int M, int N)
{
    extern __shared__ char smc[];
    uint32_t* Ap = (uint32_t*)(smc + GOFF_A);
    uint32_t* Bp = (uint32_t*)(smc + GOFF_B);
    int tid = threadIdx.x, wid = tid >> 5, lane = tid & 31;
    int g = lane >> 2, tg = lane & 3;
    int wm = wid & 1, wn = wid >> 1;
    int rm = wm * 32;
    int m0 = blockIdx.y * 64, n0 = blockIdx.x * 128;

    float acc[2][4][4];
    #pragma unroll
    for (int a = 0; a < 2; a++)
        #pragma unroll
        for (int n = 0; n < 4; n++)
            #pragma unroll
            for (int c = 0; c < 4; c++) acc[a][n][c] = 0.f;

    for (int k0 = 0; k0 < CCH; k0 += 128) {
        __syncthreads();
        for (int idx = tid; idx < 2048; idx += 256) {
            int row = idx >> 5, cl = (idx & 31) * 4;
            float4 av = *(const float4*)&A[(size_t)(m0 + row) * CCH + k0 + cl];
            uint4 ai;
            ai.x = f2tf(av.x); ai.y = f2tf(av.y); ai.z = f2tf(av.z); ai.w = f2tf(av.w);
            *(uint4*)&Ap[row * 132 + cl] = ai;
        }
        for (int idx = tid; idx < 4096; idx += 256) {
            int row = idx >> 5, cl = (idx & 31) * 4;
            float4 wv = *(const float4*)&W[(size_t)(n0 + row) * CCH + k0 + cl];
            uint4 wi;
            wi.x = f2tf(wv.x); wi.y = f2tf(wv.y); wi.z = f2tf(wv.z); wi.w = f2tf(wv.w);
            *(uint4*)&Bp[row * 132 + cl] = wi;
        }
        __syncthreads();
        #pragma unroll
        for (int ks = 0; ks < 16; ks++) {
            int kc = ks * 8;
            uint32_t af[2][4];
            #pragma unroll
            for (int mt = 0; mt < 2; mt++) {
                int r0 = (rm + mt * 16 + g) * 132 + kc + tg;
                af[mt][0] = Ap[r0];
                af[mt][1] = Ap[r0 + 8 * 132];
                af[mt][2] = Ap[r0 + 4];
                af[mt][3] = Ap[r0 + 8 * 132 + 4];
            }
            #pragma unroll
            for (int nt = 0; nt < 4; nt++) {
                int cn = wn * 32 + nt * 8;
                uint32_t b0 = Bp[(cn + g) * 132 + kc + tg];
                uint32_t b1 = Bp[(cn + g) * 132 + kc + tg + 4];
                mma8(acc[0][nt], af[0], b0, b1);
                mma8(acc[1][nt], af[1], b0, b1);
            }
        }
    }
    #pragma unroll
    for (int mt = 0; mt < 2; mt++)
    #pragma unroll
    for (int half = 0; half < 2; half++) {
        int gm = m0 + rm + mt * 16 + g + half * 8;
        #pragma unroll
        for (int nt = 0; nt < 4; nt++) {
            int gn = n0 + wn * 32 + nt * 8 + 2 * tg;
            float2 w2;
            w2.x = acc[mt][nt][half * 2 + 0];
            w2.y = acc[mt][nt][half * 2 + 1];
            if (bias != nullptr) { w2.x += bias[gn]; w2.y += bias[gn + 1]; }
            *(float2*)&C[(size_t)gm * N + gn] = w2;
        }
    }
}

// ---------------- kernel 2b: 64x128-tile fp32 GEMM (out-projection) ----------
__global__ void __launch_bounds__(256, 2) gemm2_k(const float* __restrict__ A,
                                                  const float* __restrict__ W,
                                                  const float* __restrict__ bias,
                                                  float* __restrict__ C, int M, int N)
{
    __shared__ float As[8][68];
    __shared__ float Bs[8][132];
    int m0 = blockIdx.y * 64, n0 = blockIdx.x * 128;
    int tid = threadIdx.x;
    int ty = tid >> 4, tx = tid & 15;
    int lr = tid >> 1, lk = (tid & 1) * 4;
    float accr[4][8];
    #pragma unroll
    for (int i = 0; i < 4; i++)
        #pragma unroll
        for (int j = 0; j < 8; j++) accr[i][j] = 0.f;
    for (int k0 = 0; k0 < CCH; k0 += 8) {
        float4 av = make_float4(0.f, 0.f, 0.f, 0.f);
        if (tid < 128) av = *(const float4*)&A[(size_t)(m0 + lr) * CCH + k0 + lk];
        float4 bv = *(const float4*)&W[(size_t)(n0 + lr) * CCH + k0 + lk];
        __syncthreads();
        if (tid < 128) {
            As[lk + 0][lr] = av.x; As[lk + 1][lr] = av.y;
            As[lk + 2][lr] = av.z; As[lk + 3][lr] = av.w;
        }
        Bs[lk + 0][lr] = bv.x; Bs[lk + 1][lr] = bv.y;
        Bs[lk + 2][lr] = bv.z; Bs[lk + 3][lr] = bv.w;
        __syncthreads();
        #pragma unroll
        for (int kk = 0; kk < 8; kk++) {
            float4 a0 = *(const float4*)&As[kk][ty * 4];
            float4 b0 = *(const float4*)&Bs[kk][tx * 8];
            float4 b1 = *(const float4*)&Bs[kk][tx * 8 + 4];
            float avv[4] = {a0.x, a0.y, a0.z, a0.w};
            float bvv[8] = {b0.x, b0.y, b0.z, b0.w, b1.x, b1.y, b1.z, b1.w};
            #pragma unroll
            for (int i = 0; i < 4; i++)
                #pragma unroll
                for (int j = 0; j < 8; j++)
                    accr[i][j] += avv[i] * bvv[j];
        }
    }
    #pragma unroll
    for (int i = 0; i < 4; i++) {
        int gm = m0 + ty * 4 + i;
        #pragma unroll
        for (int j = 0; j < 8; j++) {
            int gn = n0 + tx * 8 + j;
            float v = accr[i][j];
            if (bias != nullptr) v += bias[gn];
            C[(size_t)gm * N + gn] = v;
        }
    }
}

// ---------------- kernel 3: residual pre-mix over source heads ----------------
__global__ void rmix_k(const float* __restrict__ ra, const float* __restrict__ wf,
                       float* __restrict__ Rm)
{
    int s = blockIdx.x, b = blockIdx.y;
    __shared__ float w[HEADS][HEADS];
    if (threadIdx.x < 36)
        w[threadIdx.x / 6][threadIdx.x % 6] = wf[(threadIdx.x / 6) * 12 + 6 + (threadIdx.x % 6)];
    __syncthreads();
    for (int t = threadIdx.x; t < TT; t += blockDim.x) {
        float r[HEADS];
        #pragma unroll
        for (int h = 0; h < HEADS; h++)
            r[h] = ra[(((size_t)b * HEADS + h) * SS + s) * TT + t];
        #pragma unroll
        for (int o = 0; o < HEADS; o++) {
            float v = 0.f;
            #pragma unroll
            for (int h = 0; h < HEADS; h++) v += w[o][h] * r[h];
            Rm[(((size_t)b * HEADS + o) * SS + s) * TT + t] = v;
        }
    }
}

// ---------------- kernel 4: flash attention, per-head dots shared by o-pair ---
// grid (7 l-tiles, 24 = b*3+og), 256 thr = 8 warps (4m x 2n). n-warp wn owns
// output head o = og*2 + wn for AV/epilogue. Q raw bf16 resident; per-head
// 64-dot scores mixed in registers (wf*scale), bias+bilinear residual fused.
__global__ void __launch_bounds__(256, 1)
flashmma_k(const float* __restrict__ Qh, const float* __restrict__ Kh,
           const float* __restrict__ Vh, const float* __restrict__ Rm,
           const float* __restrict__ wf, const float* __restrict__ bf,
           float* __restrict__ AVo)
{
    extern __shared__ char smc[];
    uint32_t* Qp = (uint32_t*)(smc + OFF_Q);
    uint32_t* Kp = (uint32_t*)(smc + OFF_K);
    uint32_t* Pp = (uint32_t*)(smc + OFF_P);
    uint32_t* Vp = (uint32_t*)(smc + OFF_V);
    float* redmax = (float*)(smc + OFF_RM);
    float* redsum = (float*)(smc + OFF_RS);
    int*   sc00 = (int*)(smc + OFF_B0);
    int*   sc01 = (int*)(smc + OFF_B1);
    int*   sc10 = (int*)(smc + OFF_B2);
    int*   sc11 = (int*)(smc + OFF_B3);
    float* swx  = (float*)(smc + OFF_WXA);
    float* swy  = (float*)(smc + OFF_WYA);
    __shared__ float wfs_s[2][6], bfs_s[2];

    int tid = threadIdx.x, wid = tid >> 5, lane = tid & 31;
    int g = lane >> 2, tg = lane & 3;
    int wm = wid & 3, wn = wid >> 2;   // 4 m-warps, 2 n-warps
    int rm = wm * 32;
    int by = blockIdx.y;
    int b = by / 3, og = by % 3;
    int l0 = blockIdx.x * 128;

    const float scale = rsqrtf((float)CCH);
    if (tid < 12) wfs_s[tid / 6][tid % 6] = wf[(og * 2 + tid / 6) * 12 + (tid % 6)] * scale;
    if (tid < 2)  bfs_s[tid] = bf[og * 2 + tid];
    if (tid < 128) {
        int pl = min(l0 + tid, PQ - 1);
        int y = pl / 28, xx = pl % 28;
        float cy = fminf(fmaxf(y * 0.5f - 0.25f, 0.f), 13.f);
        int iy0 = (int)cy; float wy = cy - (float)iy0; int iy1 = min(iy0 + 1, 13);
        float cx = fminf(fmaxf(xx * 0.5f - 0.25f, 0.f), 13.f);
        int ix0 = (int)cx; float wx = cx - (float)ix0; int ix1 = min(ix0 + 1, 13);
        sc00[tid] = (iy0 * 14 + ix0) * TT;
        sc01[tid] = (iy0 * 14 + ix1) * TT;
        sc10[tid] = (iy1 * 14 + ix0) * TT;
        sc11[tid] = (iy1 * 14 + ix1) * TT;
        swx[tid] = wx; swy[tid] = wy;
    }
    __syncthreads();
    float wfsr[2][6], bfr[2];
    #pragma unroll
    for (int oo = 0; oo < 2; oo++) {
        bfr[oo] = bfs_s[oo];
        #pragma unroll
        for (int h = 0; h < 6; h++) wfsr[oo][h] = wfs_s[oo][h];
    }

    const float* Qb = Qh + (size_t)b * PQ * CCH;
    const float* Kb = Kh + (size_t)b * PQ * CCH;
    const float* Vb = Vh + (size_t)b * PQ * CCH + og * 128;      // o-pair channels
    const float* Ro0 = Rm + ((size_t)b * HEADS + og * 2) * SS * TT;
    const float* Ro1 = Ro0 + (size_t)SS * TT;

    // ---- Q fill: raw bf16, resident ----
    for (int idx = tid; idx < 128 * 96; idx += 256) {
        int row = idx / 96, c4 = idx % 96, cl = c4 * 4;
        float4 qv = make_float4(0.f, 0.f, 0.f, 0.f);
        if (l0 + row < PQ) qv = *(const float4*)&Qb[(size_t)(l0 + row) * CCH + cl];
        uint2 st;
        st.x = bf2(qv.x, qv.y);
        st.y = bf2(qv.z, qv.w);
        *(uint2*)&Qp[row * 196 + c4 * 2] = st;
    }

    float m_run[2][4], s_run[2][4];
    float av[2][8][4];                 // [mt][dt][c], own o = wn
    #pragma unroll
    for (int oo = 0; oo < 2; oo++)
        #pragma unroll
        for (int i = 0; i < 4; i++) { m_run[oo][i] = -1e30f; s_run[oo][i] = 0.f; }
    #pragma unroll
    for (int a = 0; a < 2; a++)
        #pragma unroll
        for (int n = 0; n < 8; n++)
            #pragma unroll
            for (int c = 0; c < 4; c++) av[a][n][c] = 0.f;

    for (int kt = 0; kt < 25; kt++) {
        int t0 = kt * 32;
        __syncthreads();   // protect K/V/P from previous consumers

        // ---- K fill (32 keys x 384ch bf16) ----
        for (int idx = tid; idx < 3072; idx += 256) {
            int row = idx / 96, c4 = idx % 96;
            float4 kv = make_float4(0.f, 0.f, 0.f, 0.f);
            if (t0 + row < PQ) kv = *(const float4*)&Kb[(size_t)(t0 + row) * CCH + c4 * 4];
            uint2 st;
            st.x = bf2(kv.x, kv.y);
            st.y = bf2(kv.z, kv.w);
            *(uint2*)&Kp[row * 196 + c4 * 2] = st;
        }
        // ---- V fill (32 keys x 128ch tf32, o-pair) ----
        for (int idx = tid; idx < 1024; idx += 256) {
            int row = idx >> 5, c4 = idx & 31;
            float4 vv = make_float4(0.f, 0.f, 0.f, 0.f);
            if (t0 + row < PQ) vv = *(const float4*)&Vb[(size_t)(t0 + row) * CCH + c4 * 4];
            uint4 vi;
            vi.x = f2tf(vv.x); vi.y = f2tf(vv.y); vi.z = f2tf(vv.z); vi.w = f2tf(vv.w);
            *(uint4*)&Vp[row * 136 + c4 * 4] = vi;
        }
        __syncthreads();

        // ---- per-head QK: 6 heads x 4 k-steps, bf16 mma16 ----
        float acc[6][2][2][4];
        #pragma unroll
        for (int h = 0; h < 6; h++)
            #pragma unroll
            for (int a = 0; a < 2; a++)
                #pragma unroll
                for (int n = 0; n < 2; n++)
                    #pragma unroll
                    for (int c = 0; c < 4; c++) acc[h][a][n][c] = 0.f;
        #pragma unroll
        for (int h = 0; h < 6; h++) {
            #pragma unroll
            for (int ks = 0; ks < 4; ks++) {
                int kw = h * 32 + ks * 8;
                uint32_t af[2][4];
                #pragma unroll
                for (int mt = 0; mt < 2; mt++) {
                    int r0 = (rm + mt * 16 + g) * 196 + kw + tg;
                    af[mt][0] = Qp[r0];
                    af[mt][1] = Qp[r0 + 8 * 196];
                    af[mt][2] = Qp[r0 + 4];
                    af[mt][3] = Qp[r0 + 8 * 196 + 4];
                }
                #pragma unroll
                for (int nt = 0; nt < 2; nt++) {
                    int cn = wn * 16 + nt * 8;
                    uint32_t b0 = Kp[(cn + g) * 196 + kw + tg];
                    uint32_t b1 = Kp[(cn + g) * 196 + kw + tg + 4];
                    mma16(acc[h][0][nt], af[0], b0, b1);
                    mma16(acc[h][1][nt], af[1], b0, b1);
                }
            }
        }

        // ---- mix in registers: both o's; bias + bilinear residual + mask ----
        float sx[2][2][2][4];
        float rmx[2][4];
        #pragma unroll
        for (int oo = 0; oo < 2; oo++)
            #pragma unroll
            for (int i = 0; i < 4; i++) rmx[oo][i] = -1e30f;
        #pragma unroll
        for (int mt = 0; mt < 2; mt++)
        #pragma unroll
        for (int half = 0; half < 2; half++) {
            int lr = rm + mt * 16 + g + half * 8;
            int o00 = sc00[lr], o01 = sc01[lr], o10 = sc10[lr], o11 = sc11[lr];
            float wx = swx[lr], wy = swy[lr];
            int hr = mt * 2 + half;
            #pragma unroll
            for (int nt = 0; nt < 2; nt++) {
                int gt = t0 + wn * 16 + nt * 8 + 2 * tg;
                if (gt < PQ) {
                    #pragma unroll
                    for (int oo = 0; oo < 2; oo++) {
                        const float* R = (oo == 0) ? Ro0 : Ro1;
                        float2 p00 = *(const float2*)&R[o00 + gt];
                        float2 p01 = *(const float2*)&R[o01 + gt];
                        float2 p10 = *(const float2*)&R[o10 + gt];
                        float2 p11 = *(const float2*)&R[o11 + gt];
                        float r0x = p00.x + (p01.x - p00.x) * wx;
                        float r1x = p10.x + (p11.x - p10.x) * wx;
                        float r0y = p00.y + (p01.y - p00.y) * wx;
                        float r1y = p10.y + (p11.y - p10.y) * wx;
                        float s0 = bfr[oo] + r0x + (r1x - r0x) * wy;
                        float s1 = bfr[oo] + r0y + (r1y - r0y) * wy;
                        #pragma unroll
                        for (int h = 0; h < 6; h++) {
                            s0 += wfsr[oo][h] * acc[h][mt][nt][half * 2 + 0];
                            s1 += wfsr[oo][h] * acc[h][mt][nt][half * 2 + 1];
                        }
                        sx[oo][mt][nt][half * 2 + 0] = s0;
                        sx[oo][mt][nt][half * 2 + 1] = s1;
                        rmx[oo][hr] = fmaxf(rmx[oo][hr], fmaxf(s0, s1));
                    }
                } else {
                    #pragma unroll
                    for (int oo = 0; oo < 2; oo++) {
                        sx[oo][mt][nt][half * 2 + 0] = -1e30f;
                        sx[oo][mt][nt][half * 2 + 1] = -1e30f;
                    }
                }
            }
        }
        #pragma unroll
        for (int oo = 0; oo < 2; oo++)
            #pragma unroll
            for (int hr = 0; hr < 4; hr++) {
                rmx[oo][hr] = fmaxf(rmx[oo][hr], __shfl_xor_sync(0xffffffffu, rmx[oo][hr], 1));
                rmx[oo][hr] = fmaxf(rmx[oo][hr], __shfl_xor_sync(0xffffffffu, rmx[oo][hr], 2));
            }
        if (tg == 0) {
            #pragma unroll
            for (int oo = 0; oo < 2; oo++)
                #pragma unroll
                for (int hr = 0; hr < 4; hr++)
                    redmax[(oo * 2 + wn) * 128 + rm + (hr >> 1) * 16 + g + (hr & 1) * 8] = rmx[oo][hr];
        }
        __syncthreads();

        float corr[2][4], mnew[2][4];
        #pragma unroll
        for (int oo = 0; oo < 2; oo++)
            #pragma unroll
            for (int hr = 0; hr < 4; hr++) {
                int lr = rm + (hr >> 1) * 16 + g + (hr & 1) * 8;
                float mt2 = fmaxf(redmax[(oo * 2 + 0) * 128 + lr], redmax[(oo * 2 + 1) * 128 + lr]);
                mnew[oo][hr] = fmaxf(m_run[oo][hr], mt2);
                corr[oo][hr] = __expf(m_run[oo][hr] - mnew[oo][hr]);
                m_run[oo][hr] = mnew[oo][hr];
            }
        float psum[2][4];
        #pragma unroll
        for (int oo = 0; oo < 2; oo++)
            #pragma unroll
            for (int i = 0; i < 4; i++) psum[oo][i] = 0.f;
        #pragma unroll
        for (int oo = 0; oo < 2; oo++)
            #pragma unroll
            for (int mt = 0; mt < 2; mt++)
                #pragma unroll
                for (int nt = 0; nt < 2; nt++)
                    #pragma unroll
                    for (int c = 0; c < 4; c++) {
                        int hr = mt * 2 + (c >> 1);
                        float e = __expf(sx[oo][mt][nt][c] - mnew[oo][hr]);
                        sx[oo][mt][nt][c] = e;
                        psum[oo][hr] += e;
                    }
        #pragma unroll
        for (int oo = 0; oo < 2; oo++)
            #pragma unroll
            for (int hr = 0; hr < 4; hr++) {
                psum[oo][hr] += __shfl_xor_sync(0xffffffffu, psum[oo][hr], 1);
                psum[oo][hr] += __shfl_xor_sync(0xffffffffu, psum[oo][hr], 2);
            }
        if (tg == 0) {
            #pragma unroll
            for (int oo = 0; oo < 2; oo++)
                #pragma unroll
                for (int hr = 0; hr < 4; hr++)
                    redsum[(oo * 2 + wn) * 128 + rm + (hr >> 1) * 16 + g + (hr & 1) * 8] = psum[oo][hr];
        }
        __syncthreads();
        #pragma unroll
        for (int oo = 0; oo < 2; oo++)
            #pragma unroll
            for (int hr = 0; hr < 4; hr++) {
                int lr = rm + (hr >> 1) * 16 + g + (hr & 1) * 8;
                s_run[oo][hr] = s_run[oo][hr] * corr[oo][hr]
                              + redsum[(oo * 2 + 0) * 128 + lr] + redsum[(oo * 2 + 1) * 128 + lr];
            }
        // rescale own-o AV accumulators
        #pragma unroll
        for (int mt = 0; mt < 2; mt++)
            #pragma unroll
            for (int dt = 0; dt < 8; dt++)
                #pragma unroll
                for (int c = 0; c < 4; c++)
                    av[mt][dt][c] *= corr[wn][mt * 2 + (c >> 1)];

        // ---- store P (tf32) both o's ----
        #pragma unroll
        for (int oo = 0; oo < 2; oo++)
            #pragma unroll
            for (int mt = 0; mt < 2; mt++)
                #pragma unroll
                for (int half = 0; half < 2; half++) {
                    int lr = rm + mt * 16 + g + half * 8;
                    #pragma unroll
                    for (int nt = 0; nt < 2; nt++) {
                        uint2 pv;
                        pv.x = f2tf(sx[oo][mt][nt][half * 2 + 0]);
                        pv.y = f2tf(sx[oo][mt][nt][half * 2 + 1]);
                        *(uint2*)&Pp[oo * 4608 + lr * 36 + wn * 16 + nt * 8 + 2 * tg] = pv;
                    }
                }
        __syncthreads();

        // ---- AV for own o: tf32 mma8, k=32, d-tile 64 per warp ----
        const uint32_t* Pown = Pp + wn * 4608;
        #pragma unroll
        for (int ks = 0; ks < 4; ks++) {
            int kc = ks * 8;
            uint32_t af[2][4];
            #pragma unroll
            for (int mt = 0; mt < 2; mt++) {
                int r0 = (rm + mt * 16 + g) * 36 + kc + tg;
                af[mt][0] = Pown[r0];
                af[mt][1] = Pown[r0 + 8 * 36];
                af[mt][2] = Pown[r0 + 4];
                af[mt][3] = Pown[r0 + 8 * 36 + 4];
            }
            #pragma unroll
            for (int dt = 0; dt < 8; dt++) {
                int cn = wn * 64 + dt * 8;
                uint32_t b0 = Vp[(kc + tg) * 136 + cn + g];
                uint32_t b1 = Vp[(kc + tg + 4) * 136 + cn + g];
                mma8(av[0][dt], af[0], b0, b1);
                mma8(av[1][dt], af[1], b0, b1);
            }
        }
    }

    // ===== epilogue: own o = og*2 + wn =====
    float inv[4];
    #pragma unroll
    for (int hr = 0; hr < 4; hr++) inv[hr] = 1.f / s_run[wn][hr];
    #pragma unroll
    for (int mt = 0; mt < 2; mt++)
    #pragma unroll
    for (int half = 0; half < 2; half++) {
        int gl = l0 + rm + mt * 16 + g + half * 8;
        if (gl < PQ) {
            int hr = mt * 2 + half;
            float* op = AVo + ((size_t)b * PQ + gl) * CCH + (og * 2 + wn) * DH;
            #pragma unroll
            for (int dt = 0; dt < 8; dt++) {
                float2 w2;
                w2.x = av[mt][dt][half * 2 + 0] * inv[hr];
                w2.y = av[mt][dt][half * 2 + 1] * inv[hr];
                *(float2*)&op[dt * 8 + 2 * tg] = w2;
            }
        }
    }
}

// ---------------- launcher ----------------------------------------------------
extern "C" void kernel_launch(void* const* d_in, const int* in_sizes, int n_in,
                              void* d_out, int out_size)
{
    const float* x   = (const float*)d_in[0];
    const float* ra  = (const float*)d_in[1];
    const float* cw  = (const float*)d_in[2];
    const float* lng = (const float*)d_in[3];
    const float* lnb = (const float*)d_in[4];
    const float* wq  = (const float*)d_in[5];
    const float* wk  = (const float*)d_in[6];
    const float* wv  = (const float*)d_in[7];
    const float* wp  = (const float*)d_in[8];
    const float* bp  = (const float*)d_in[9];
    const float* wf  = (const float*)d_in[10];
    const float* bf  = (const float*)d_in[11];
    float* out = (float*)d_out;

    float *Qln, *KV, *Qh, *Kh, *Vh, *Rm, *AV;
    cudaGetSymbolAddress((void**)&Qln, g_Qln);
    cudaGetSymbolAddress((void**)&KV,  g_KV);
    cudaGetSymbolAddress((void**)&Qh,  g_Qh);
    cudaGetSymbolAddress((void**)&Kh,  g_Kh);
    cudaGetSymbolAddress((void**)&Vh,  g_Vh);
    cudaGetSymbolAddress((void**)&Rm,  g_Rm);
    cudaGetSymbolAddress((void**)&AV,  g_AV);

    prep_k<<<dim3(PQ, BATCH), CCH>>>(x, cw, lng, lnb, Qln, KV);

    cudaFuncSetAttribute(gemm_tc, cudaFuncAttributeMaxDynamicSharedMemorySize, GSMT);
    gemm_tc<<<dim3(3, 98), 256, GSMT>>>(Qln, wq, nullptr, Qh, BATCH * PQ, CCH);
    gemm_tc<<<dim3(3, 98), 256, GSMT>>>(KV,  wk, nullptr, Kh, BATCH * PQ, CCH);
    gemm_tc<<<dim3(3, 98), 256, GSMT>>>(KV,  wv, nullptr, Vh, BATCH * PQ, CCH);

    rmix_k<<<dim3(SS, BATCH), 256>>>(ra, wf, Rm);

    cudaFuncSetAttribute(flashmma_k, cudaFuncAttributeMaxDynamicSharedMemorySize, SMT);
    flashmma_k<<<dim3(7, BATCH * 3), 256, SMT>>>(Qh, Kh, Vh, Rm, wf, bf, AV);

    gemm2_k<<<dim3(3, 98), 256>>>(AV, wp, bp, out, BATCH * PQ, CCH);
}

// round 15
// speedup vs baseline: 1.3085x; 1.3085x over previous
#include <cuda_runtime.h>
#include <cstdint>
#include <cstddef>

#define BATCH 8
#define HH 56
#define WW 56
#define CCH 384
#define HEADS 6
#define DH 64
#define PQ 784
#define SS 196
#define TT 784

__device__ float g_Qln[BATCH * PQ * CCH];
__device__ float g_KV [BATCH * PQ * CCH];
__device__ float g_Qh [BATCH * PQ * CCH];
__device__ float g_Kh [BATCH * PQ * CCH];
__device__ float g_Vh [BATCH * PQ * CCH];
__device__ float g_Rm [BATCH * HEADS * SS * TT];
__device__ float g_AV [BATCH * PQ * CCH];

// ---------------- mma helpers ----------------
__device__ __forceinline__ uint32_t f2tf(float f) {
    uint32_t r; asm("cvt.rna.tf32.f32 %0, %1;" : "=r"(r) : "f"(f)); return r;
}
__device__ __forceinline__ uint32_t bf2(float lo, float hi) {
    uint32_t r; asm("cvt.rn.bf16x2.f32 %0, %1, %2;" : "=r"(r) : "f"(hi), "f"(lo)); return r;
}
__device__ __forceinline__ void mma8(float* d, const uint32_t* a, uint32_t b0, uint32_t b1) {
    asm volatile("mma.sync.aligned.m16n8k8.row.col.f32.tf32.tf32.f32 "
        "{%0,%1,%2,%3}, {%4,%5,%6,%7}, {%8,%9}, {%0,%1,%2,%3};"
        : "+f"(d[0]), "+f"(d[1]), "+f"(d[2]), "+f"(d[3])
        : "r"(a[0]), "r"(a[1]), "r"(a[2]), "r"(a[3]), "r"(b0), "r"(b1));
}
__device__ __forceinline__ void mma16(float* d, const uint32_t* a, uint32_t b0, uint32_t b1) {
    asm volatile("mma.sync.aligned.m16n8k16.row.col.f32.bf16.bf16.f32 "
        "{%0,%1,%2,%3}, {%4,%5,%6,%7}, {%8,%9}, {%0,%1,%2,%3};"
        : "+f"(d[0]), "+f"(d[1]), "+f"(d[2]), "+f"(d[3])
        : "r"(a[0]), "r"(a[1]), "r"(a[2]), "r"(a[3]), "r"(b0), "r"(b1));
}

// flash smem map (bytes). Q resident bf16 (stride 196 u32). K chunk bf16 (stride 68).
// P tf32 (stride 132) aliases K region (phase-disjoint). V tf32 (stride 72) disjoint.
#define OFF_Q   0
#define OFF_K   100352
#define OFF_P   100352
#define OFF_V   167936
#define OFF_RM  204800
#define OFF_RS  205824
#define OFF_B0  206848
#define OFF_B1  207360
#define OFF_B2  207872
#define OFF_B3  208384
#define OFF_WXA 208896
#define OFF_WYA 209408
#define SMT     209920

// gemm_tc smem
#define GOFF_A 0
#define GOFF_B 67584
#define GSMT   135168

// ---------------- kernel 1: depthwise conv + LN + 2x2 avgpool ----------------
__global__ void prep_k(const float* __restrict__ x, const float* __restrict__ cw,
                       const float* __restrict__ lng, const float* __restrict__ lnb,
                       float* __restrict__ Qln, float* __restrict__ KV)
{
    int p = blockIdx.x, b = blockIdx.y, c = threadIdx.x;
    int oy = p / 28, ox = p % 28;
    const float* xb = x + (size_t)b * (HH * WW) * CCH;
    float acc = 0.f;
    #pragma unroll
    for (int dy = 0; dy < 3; dy++) {
        int y = 2 * oy + dy - 1;
        if ((unsigned)y < (unsigned)HH) {
            #pragma unroll
            for (int dx = 0; dx < 3; dx++) {
                int xx = 2 * ox + dx - 1;
                if ((unsigned)xx < (unsigned)WW)
                    acc += xb[(size_t)(y * WW + xx) * CCH + c] * cw[c * 9 + dy * 3 + dx];
            }
        }
    }
    int py = 2 * oy, px = 2 * ox;
    float pv = 0.25f * (xb[(size_t)(py * WW + px) * CCH + c] +
                        xb[(size_t)(py * WW + px + 1) * CCH + c] +
                        xb[(size_t)((py + 1) * WW + px) * CCH + c] +
                        xb[(size_t)((py + 1) * WW + px + 1) * CCH + c]);
    KV[((size_t)b * PQ + p) * CCH + c] = pv;

    __shared__ float ssum[CCH], ssq[CCH];
    ssum[c] = acc; ssq[c] = acc * acc;
    __syncthreads();
    if (c < 128) { ssum[c] += ssum[c + 128] + ssum[c + 256];
                   ssq [c] += ssq [c + 128] + ssq [c + 256]; }
    __syncthreads();
    for (int s = 64; s > 0; s >>= 1) {
        if (c < s) { ssum[c] += ssum[c + s]; ssq[c] += ssq[c + s]; }
        __syncthreads();
    }
    float mu  = ssum[0] * (1.f / CCH);
    float var = ssq[0] * (1.f / CCH) - mu * mu;
    float inv = rsqrtf(var + 1e-5f);
    Qln[((size_t)b * PQ + p) * CCH + c] = (acc - mu) * inv * lng[c] + lnb[c];
}

// ---------------- kernel 2: tf32 tensor GEMM, C = A*W^T (+bias) --------------
// blocks 128x128, 8 warps (4x2), warp tile 32x64.
__global__ void __launch_bounds__(256, 1) gemm_tc(const float* __restrict__ A,
                                                  const float* __restrict__ W,
                                                  const float* __restrict__ bias,
                                                  float* __restrict__ C, int M, int N)
{
    extern __shared__ char smc[];
    uint32_t* Ap = (uint32_t*)(smc + GOFF_A);   // [128][132]
    uint32_t* Bp = (uint32_t*)(smc + GOFF_B);   // [128][132]
    int tid = threadIdx.x, wid = tid >> 5, lane = tid & 31;
    int g = lane >> 2, tg = lane & 3;
    int wm = wid & 3, wn = wid >> 2;
    int rm = wm * 32;
    int m0 = blockIdx.y * 128, n0 = blockIdx.x * 128;

    float acc[2][8][4];
    #pragma unroll
    for (int a = 0; a < 2; a++)
        #pragma unroll
        for (int n = 0; n < 8; n++)
            #pragma unroll
            for (int c = 0; c < 4; c++) acc[a][n][c] = 0.f;

    for (int k0 = 0; k0 < CCH; k0 += 128) {
        __syncthreads();
        for (int idx = tid; idx < 4096; idx += 256) {
            int row = idx >> 5, cl = (idx & 31) * 4;
            float4 av = *(const float4*)&A[(size_t)(m0 + row) * CCH + k0 + cl];
            float4 wv = *(const float4*)&W[(size_t)(n0 + row) * CCH + k0 + cl];
            uint4 ai, wi;
            ai.x = f2tf(av.x); ai.y = f2tf(av.y); ai.z = f2tf(av.z); ai.w = f2tf(av.w);
            wi.x = f2tf(wv.x); wi.y = f2tf(wv.y); wi.z = f2tf(wv.z); wi.w = f2tf(wv.w);
            *(uint4*)&Ap[row * 132 + cl] = ai;
            *(uint4*)&Bp[row * 132 + cl] = wi;
        }
        __syncthreads();
        #pragma unroll
        for (int ks = 0; ks < 16; ks++) {
            int kc = ks * 8;
            uint32_t af[2][4];
            #pragma unroll
            for (int mt = 0; mt < 2; mt++) {
                int r0 = (rm + mt * 16 + g) * 132 + kc + tg;
                af[mt][0] = Ap[r0];
                af[mt][1] = Ap[r0 + 8 * 132];
                af[mt][2] = Ap[r0 + 4];
                af[mt][3] = Ap[r0 + 8 * 132 + 4];
            }
            #pragma unroll
            for (int nt = 0; nt < 8; nt++) {
                int cn = wn * 64 + nt * 8;
                uint32_t b0 = Bp[(cn + g) * 132 + kc + tg];
                uint32_t b1 = Bp[(cn + g) * 132 + kc + tg + 4];
                mma8(acc[0][nt], af[0], b0, b1);
                mma8(acc[1][nt], af[1], b0, b1);
            }
        }
    }
    #pragma unroll
    for (int mt = 0; mt < 2; mt++)
    #pragma unroll
    for (int half = 0; half < 2; half++) {
        int gm = m0 + rm + mt * 16 + g + half * 8;
        #pragma unroll
        for (int nt = 0; nt < 8; nt++) {
            int gn = n0 + wn * 64 + nt * 8 + 2 * tg;
            float2 w2;
            w2.x = acc[mt][nt][half * 2 + 0];
            w2.y = acc[mt][nt][half * 2 + 1];
            if (bias != nullptr) { w2.x += bias[gn]; w2.y += bias[gn + 1]; }
            *(float2*)&C[(size_t)gm * N + gn] = w2;
        }
    }
}

// ---------------- kernel 3: residual pre-mix over source heads ----------------
__global__ void rmix_k(const float* __restrict__ ra, const float* __restrict__ wf,
                       float* __restrict__ Rm)
{
    int s = blockIdx.x, b = blockIdx.y;
    __shared__ float w[HEADS][HEADS];
    if (threadIdx.x < 36)
        w[threadIdx.x / 6][threadIdx.x % 6] = wf[(threadIdx.x / 6) * 12 + 6 + (threadIdx.x % 6)];
    __syncthreads();
    for (int t = threadIdx.x; t < TT; t += blockDim.x) {
        float r[HEADS];
        #pragma unroll
        for (int h = 0; h < HEADS; h++)
            r[h] = ra[(((size_t)b * HEADS + h) * SS + s) * TT + t];
        #pragma unroll
        for (int o = 0; o < HEADS; o++) {
            float v = 0.f;
            #pragma unroll
            for (int h = 0; h < HEADS; h++) v += w[o][h] * r[h];
            Rm[(((size_t)b * HEADS + o) * SS + s) * TT + t] = v;
        }
    }
}

// ---------------- kernel 4: flash attention (bf16 QK + tf32 PV) ---------------
// grid (7 q-tiles, 48 (b,o)), 256 thr = 8 warps (4x2). Q' resident in smem.
__global__ void __launch_bounds__(256, 1)
flashmma_k(const float* __restrict__ Qh, const float* __restrict__ Kh,
           const float* __restrict__ Vh, const float* __restrict__ Rm,
           const float* __restrict__ wf, const float* __restrict__ bf,
           float* __restrict__ AVo)
{
    extern __shared__ char smc[];
    uint32_t* Qp = (uint32_t*)(smc + OFF_Q);   // bf16x2, row stride 196 u32
    uint32_t* Kp = (uint32_t*)(smc + OFF_K);   // bf16x2, row stride 68 u32
    uint32_t* Pp = (uint32_t*)(smc + OFF_P);   // tf32,   row stride 132 u32
    uint32_t* Vp = (uint32_t*)(smc + OFF_V);   // tf32,   row stride 72 u32
    float* redmax = (float*)(smc + OFF_RM);
    float* redsum = (float*)(smc + OFF_RS);
    int*   sc00 = (int*)(smc + OFF_B0);
    int*   sc01 = (int*)(smc + OFF_B1);
    int*   sc10 = (int*)(smc + OFF_B2);
    int*   sc11 = (int*)(smc + OFF_B3);
    float* swx  = (float*)(smc + OFF_WXA);
    float* swy  = (float*)(smc + OFF_WYA);
    __shared__ float qscs[8];

    int tid = threadIdx.x, wid = tid >> 5, lane = tid & 31;
    int g = lane >> 2, tg = lane & 3;
    int wm = wid & 3, wn = wid >> 2;
    int rm = wm * 32;
    int bo = blockIdx.y, b = bo / HEADS, o = bo % HEADS;
    int l0 = blockIdx.x * 128;

    const float scale = rsqrtf((float)CCH);
    if (tid < 6) qscs[tid] = wf[o * 12 + tid] * scale;
    if (tid == 6) qscs[6] = bf[o];
    if (tid < 128) {
        int pl = min(l0 + tid, PQ - 1);
        int y = pl / 28, xx = pl % 28;
        float cy = fminf(fmaxf(y * 0.5f - 0.25f, 0.f), 13.f);
        int iy0 = (int)cy; float wy = cy - (float)iy0; int iy1 = min(iy0 + 1, 13);
        float cx = fminf(fmaxf(xx * 0.5f - 0.25f, 0.f), 13.f);
        int ix0 = (int)cx; float wx = cx - (float)ix0; int ix1 = min(ix0 + 1, 13);
        sc00[tid] = (iy0 * 14 + ix0) * TT;
        sc01[tid] = (iy0 * 14 + ix1) * TT;
        sc10[tid] = (iy1 * 14 + ix0) * TT;
        sc11[tid] = (iy1 * 14 + ix1) * TT;
        swx[tid] = wx; swy[tid] = wy;
    }
    __syncthreads();
    const float biasv = qscs[6];

    const float* Qb = Qh + (size_t)b * PQ * CCH;
    const float* Kb = Kh + (size_t)b * PQ * CCH;
    const float* Vb = Vh + (size_t)b * PQ * CCH + o * DH;
    const float* Ro = Rm + (size_t)bo * SS * TT;

    // ---- Q' fill: scaled, bf16, resident for whole block ----
    for (int idx = tid; idx < 128 * 96; idx += 256) {
        int row = idx / 96, c4 = idx % 96, cl = c4 * 4;
        float4 qv = make_float4(0.f, 0.f, 0.f, 0.f);
        if (l0 + row < PQ) qv = *(const float4*)&Qb[(size_t)(l0 + row) * CCH + cl];
        float wqv = qscs[cl >> 6];
        uint2 st;
        st.x = bf2(qv.x * wqv, qv.y * wqv);
        st.y = bf2(qv.z * wqv, qv.w * wqv);
        *(uint2*)&Qp[row * 196 + c4 * 2] = st;
    }

    float m_run[4], s_run[4];
    float av[2][4][4];
    #pragma unroll
    for (int i = 0; i < 4; i++) { m_run[i] = -1e30f; s_run[i] = 0.f; }
    #pragma unroll
    for (int a = 0; a < 2; a++)
        #pragma unroll
        for (int n = 0; n < 4; n++)
            #pragma unroll
            for (int c = 0; c < 4; c++) av[a][n][c] = 0.f;

    for (int kt = 0; kt < 7; kt++) {
        int t0 = kt * 128;
        float sacc[2][8][4];
        #pragma unroll
        for (int a = 0; a < 2; a++)
            #pragma unroll
            for (int n = 0; n < 8; n++)
                #pragma unroll
                for (int c = 0; c < 4; c++) sacc[a][n][c] = 0.f;

        // ===== QK^T: 3 chunks of 128 cols, bf16 m16n8k16 =====
        for (int cc = 0; cc < 3; cc++) {
            int c0 = cc * 128;
            __syncthreads();
            for (int idx = tid; idx < 4096; idx += 256) {
                int row = idx >> 5, c4 = idx & 31, cl = c4 * 4;
                float4 kv = make_float4(0.f, 0.f, 0.f, 0.f);
                if (t0 + row < PQ) kv = *(const float4*)&Kb[(size_t)(t0 + row) * CCH + c0 + cl];
                uint2 st;
                st.x = bf2(kv.x, kv.y);
                st.y = bf2(kv.z, kv.w);
                *(uint2*)&Kp[row * 68 + c4 * 2] = st;
            }
            __syncthreads();
            #pragma unroll
            for (int ks = 0; ks < 8; ks++) {
                int kw = ks * 8;
                uint32_t af[2][4];
                #pragma unroll
                for (int mt = 0; mt < 2; mt++) {
                    int r0 = (rm + mt * 16 + g) * 196 + cc * 64 + kw + tg;
                    af[mt][0] = Qp[r0];
                    af[mt][1] = Qp[r0 + 8 * 196];
                    af[mt][2] = Qp[r0 + 4];
                    af[mt][3] = Qp[r0 + 8 * 196 + 4];
                }
                #pragma unroll
                for (int nt = 0; nt < 8; nt++) {
                    int cn = wn * 64 + nt * 8;
                    uint32_t b0 = Kp[(cn + g) * 68 + kw + tg];
                    uint32_t b1 = Kp[(cn + g) * 68 + kw + tg + 4];
                    mma16(sacc[0][nt], af[0], b0, b1);
                    mma16(sacc[1][nt], af[1], b0, b1);
                }
            }
        }

        // ===== bias + bilinear residual + mask, row max =====
        float rmax[4] = {-1e30f, -1e30f, -1e30f, -1e30f};
        #pragma unroll
        for (int mt = 0; mt < 2; mt++)
        #pragma unroll
        for (int half = 0; half < 2; half++) {
            int lr = rm + mt * 16 + g + half * 8;
            int o00 = sc00[lr], o01 = sc01[lr], o10 = sc10[lr], o11 = sc11[lr];
            float wx = swx[lr], wy = swy[lr];
            int hr = mt * 2 + half;
            #pragma unroll
            for (int nt = 0; nt < 8; nt++) {
                int gt = t0 + wn * 64 + nt * 8 + 2 * tg;
                float v0, v1;
                if (gt < PQ) {
                    float2 p00 = *(const float2*)&Ro[o00 + gt];
                    float2 p01 = *(const float2*)&Ro[o01 + gt];
                    float2 p10 = *(const float2*)&Ro[o10 + gt];
                    float2 p11 = *(const float2*)&Ro[o11 + gt];
                    float r0x = p00.x + (p01.x - p00.x) * wx;
                    float r1x = p10.x + (p11.x - p10.x) * wx;
                    float r0y = p00.y + (p01.y - p00.y) * wx;
                    float r1y = p10.y + (p11.y - p10.y) * wx;
                    v0 = sacc[mt][nt][half * 2 + 0] + biasv + r0x + (r1x - r0x) * wy;
                    v1 = sacc[mt][nt][half * 2 + 1] + biasv + r0y + (r1y - r0y) * wy;
                } else { v0 = -1e30f; v1 = -1e30f; }
                sacc[mt][nt][half * 2 + 0] = v0;
                sacc[mt][nt][half * 2 + 1] = v1;
                rmax[hr] = fmaxf(rmax[hr], fmaxf(v0, v1));
            }
        }
        #pragma unroll
        for (int hr = 0; hr < 4; hr++) {
            rmax[hr] = fmaxf(rmax[hr], __shfl_xor_sync(0xffffffffu, rmax[hr], 1));
            rmax[hr] = fmaxf(rmax[hr], __shfl_xor_sync(0xffffffffu, rmax[hr], 2));
        }
        if (tg == 0) {
            #pragma unroll
            for (int hr = 0; hr < 4; hr++)
                redmax[wn * 128 + rm + (hr >> 1) * 16 + g + (hr & 1) * 8] = rmax[hr];
        }
        __syncthreads();

        float corr[4], mnew[4];
        #pragma unroll
        for (int hr = 0; hr < 4; hr++) {
            int lr = rm + (hr >> 1) * 16 + g + (hr & 1) * 8;
            float mt2 = fmaxf(redmax[lr], redmax[128 + lr]);
            mnew[hr] = fmaxf(m_run[hr], mt2);
            corr[hr] = __expf(m_run[hr] - mnew[hr]);
            m_run[hr] = mnew[hr];
        }
        float psum[4] = {0.f, 0.f, 0.f, 0.f};
        #pragma unroll
        for (int mt = 0; mt < 2; mt++)
            #pragma unroll
            for (int nt = 0; nt < 8; nt++)
                #pragma unroll
                for (int c = 0; c < 4; c++) {
                    int hr = mt * 2 + (c >> 1);
                    float e = __expf(sacc[mt][nt][c] - mnew[hr]);
                    sacc[mt][nt][c] = e;
                    psum[hr] += e;
                }
        #pragma unroll
        for (int hr = 0; hr < 4; hr++) {
            psum[hr] += __shfl_xor_sync(0xffffffffu, psum[hr], 1);
            psum[hr] += __shfl_xor_sync(0xffffffffu, psum[hr], 2);
        }
        if (tg == 0) {
            #pragma unroll
            for (int hr = 0; hr < 4; hr++)
                redsum[wn * 128 + rm + (hr >> 1) * 16 + g + (hr & 1) * 8] = psum[hr];
        }
        __syncthreads();
        #pragma unroll
        for (int hr = 0; hr < 4; hr++) {
            int lr = rm + (hr >> 1) * 16 + g + (hr & 1) * 8;
            s_run[hr] = s_run[hr] * corr[hr] + redsum[lr] + redsum[128 + lr];
        }
        #pragma unroll
        for (int mt = 0; mt < 2; mt++)
            #pragma unroll
            for (int nt = 0; nt < 4; nt++)
                #pragma unroll
                for (int c = 0; c < 4; c++)
                    av[mt][nt][c] *= corr[mt * 2 + (c >> 1)];

        // ===== store P (tf32) to smem (aliases K region; safe after syncs) =====
        #pragma unroll
        for (int mt = 0; mt < 2; mt++)
        #pragma unroll
        for (int half = 0; half < 2; half++) {
            int lr = rm + mt * 16 + g + half * 8;
            #pragma unroll
            for (int nt = 0; nt < 8; nt++) {
                uint2 pv;
                pv.x = f2tf(sacc[mt][nt][half * 2 + 0]);
                pv.y = f2tf(sacc[mt][nt][half * 2 + 1]);
                *(uint2*)&Pp[lr * 132 + wn * 64 + nt * 8 + 2 * tg] = pv;
            }
        }
        // ===== V fill (tf32) =====
        for (int idx = tid; idx < 2048; idx += 256) {
            int row = idx >> 4, dl = (idx & 15) * 4;
            float4 vv = make_float4(0.f, 0.f, 0.f, 0.f);
            if (t0 + row < PQ) vv = *(const float4*)&Vb[(size_t)(t0 + row) * CCH + dl];
            uint4 vi;
            vi.x = f2tf(vv.x); vi.y = f2tf(vv.y); vi.z = f2tf(vv.z); vi.w = f2tf(vv.w);
            *(uint4*)&Vp[row * 72 + dl] = vi;
        }
        __syncthreads();

        // ===== AV += P * V (tf32, 16 k-steps over 128 t) =====
        #pragma unroll
        for (int k = 0; k < 16; k++) {
            int kc = k * 8;
            uint32_t af[2][4];
            #pragma unroll
            for (int mt = 0; mt < 2; mt++) {
                int r0 = (rm + mt * 16 + g) * 132 + kc + tg;
                af[mt][0] = Pp[r0];
                af[mt][1] = Pp[r0 + 8 * 132];
                af[mt][2] = Pp[r0 + 4];
                af[mt][3] = Pp[r0 + 8 * 132 + 4];
            }
            #pragma unroll
            for (int nt = 0; nt < 4; nt++) {
                int cn = wn * 32 + nt * 8;
                uint32_t b0 = Vp[(kc + tg) * 72 + cn + g];
                uint32_t b1 = Vp[(kc + tg + 4) * 72 + cn + g];
                mma8(av[0][nt], af[0], b0, b1);
                mma8(av[1][nt], af[1], b0, b1);
            }
        }
    }

    // ===== epilogue =====
    float inv[4];
    #pragma unroll
    for (int hr = 0; hr < 4; hr++) inv[hr] = 1.f / s_run[hr];
    #pragma unroll
    for (int mt = 0; mt < 2; mt++)
    #pragma unroll
    for (int half = 0; half < 2; half++) {
        int gl = l0 + rm + mt * 16 + g + half * 8;
        if (gl < PQ) {
            int hr = mt * 2 + half;
            float* op = AVo + ((size_t)b * PQ + gl) * CCH + o * DH + wn * 32;
            #pragma unroll
            for (int nt = 0; nt < 4; nt++) {
                float2 w2;
                w2.x = av[mt][nt][half * 2 + 0] * inv[hr];
                w2.y = av[mt][nt][half * 2 + 1] * inv[hr];
                *(float2*)&op[nt * 8 + 2 * tg] = w2;
            }
        }
    }
}

// ---------------- launcher ----------------------------------------------------
extern "C" void kernel_launch(void* const* d_in, const int* in_sizes, int n_in,
                              void* d_out, int out_size)
{
    const float* x   = (const float*)d_in[0];
    const float* ra  = (const float*)d_in[1];
    const float* cw  = (const float*)d_in[2];
    const float* lng = (const float*)d_in[3];
    const float* lnb = (const float*)d_in[4];
    const float* wq  = (const float*)d_in[5];
    const float* wk  = (const float*)d_in[6];
    const float* wv  = (const float*)d_in[7];
    const float* wp  = (const float*)d_in[8];
    const float* bp  = (const float*)d_in[9];
    const float* wf  = (const float*)d_in[10];
    const float* bf  = (const float*)d_in[11];
    float* out = (float*)d_out;

    float *Qln, *KV, *Qh, *Kh, *Vh, *Rm, *AV;
    cudaGetSymbolAddress((void**)&Qln, g_Qln);
    cudaGetSymbolAddress((void**)&KV,  g_KV);
    cudaGetSymbolAddress((void**)&Qh,  g_Qh);
    cudaGetSymbolAddress((void**)&Kh,  g_Kh);
    cudaGetSymbolAddress((void**)&Vh,  g_Vh);
    cudaGetSymbolAddress((void**)&Rm,  g_Rm);
    cudaGetSymbolAddress((void**)&AV,  g_AV);

    prep_k<<<dim3(PQ, BATCH), CCH>>>(x, cw, lng, lnb, Qln, KV);

    const int M = BATCH * PQ;
    cudaFuncSetAttribute(gemm_tc, cudaFuncAttributeMaxDynamicSharedMemorySize, GSMT);
    gemm_tc<<<dim3(3, 49), 256, GSMT>>>(Qln, wq, nullptr, Qh, M, CCH);
    gemm_tc<<<dim3(3, 49), 256, GSMT>>>(KV,  wk, nullptr, Kh, M, CCH);
    gemm_tc<<<dim3(3, 49), 256, GSMT>>>(KV,  wv, nullptr, Vh, M, CCH);

    rmix_k<<<dim3(SS, BATCH), 256>>>(ra, wf, Rm);

    cudaFuncSetAttribute(flashmma_k, cudaFuncAttributeMaxDynamicSharedMemorySize, SMT);
    flashmma_k<<<dim3(7, BATCH * HEADS), 256, SMT>>>(Qh, Kh, Vh, Rm, wf, bf, AV);

    // out-projection now on tf32 tensor path (single change vs R10 best)
    gemm_tc<<<dim3(3, 49), 256, GSMT>>>(AV, wp, bp, out, M, CCH);
}